// round 16
// baseline (speedup 1.0000x reference)
#include <cuda_runtime.h>
#include <cuda_fp16.h>
#include <math.h>
#include <stdint.h>

#define NB 4
#define NT 4096
#define NS 4096
#define ND 512
#define NH 8
#define NHD 64

// Scratch (allocation-free rule: __device__ globals)
__device__ __half g_q[NB * NH * NT * NHD];
__device__ __half g_k[NB * NH * NS * NHD];
__device__ __half g_v[NB * NH * NS * NHD];
__device__ __half g_ah[3 * NB * NT * ND];   // fp16 query|key|value
__device__ __half g_wh[4 * ND * ND];        // hi split of Wq|Wk|Wv|Wo
__device__ __half g_wl[4 * ND * ND];
__device__ __half g_oh[NB * NT * ND];       // attention output (fp16)

// ===========================================================================
// helpers
// ===========================================================================
__device__ __forceinline__ float ex2f(float x) {
    float y;
    asm("ex2.approx.ftz.f32 %0, %1;" : "=f"(y) : "f"(x));
    return y;
}
__device__ __forceinline__ uint32_t packh2(float lo, float hi) {
    __half2 h = __floats2half2_rn(lo, hi);
    return *reinterpret_cast<uint32_t*>(&h);
}
__device__ __forceinline__ uint32_t cvta_s(const void* p) {
    return (uint32_t)__cvta_generic_to_shared(p);
}
// D += A * B  (m16n8k16 fp16 in, fp32 accum; A row-major, B col-major)
__device__ __forceinline__ void mma_f16(float* d, const uint32_t* a,
                                        uint32_t b0, uint32_t b1) {
    asm volatile(
        "mma.sync.aligned.m16n8k16.row.col.f32.f16.f16.f32 "
        "{%0,%1,%2,%3}, {%4,%5,%6,%7}, {%8,%9}, {%0,%1,%2,%3};"
        : "+f"(d[0]), "+f"(d[1]), "+f"(d[2]), "+f"(d[3])
        : "r"(a[0]), "r"(a[1]), "r"(a[2]), "r"(a[3]), "r"(b0), "r"(b1));
}
__device__ __forceinline__ void ldsm4(uint32_t* r, uint32_t addr) {
    asm volatile("ldmatrix.sync.aligned.m8n8.x4.shared.b16 {%0,%1,%2,%3}, [%4];"
                 : "=r"(r[0]), "=r"(r[1]), "=r"(r[2]), "=r"(r[3]) : "r"(addr));
}
__device__ __forceinline__ void ldsm4t(uint32_t* r, uint32_t addr) {
    asm volatile("ldmatrix.sync.aligned.m8n8.x4.trans.shared.b16 {%0,%1,%2,%3}, [%4];"
                 : "=r"(r[0]), "=r"(r[1]), "=r"(r[2]), "=r"(r[3]) : "r"(addr));
}
__device__ __forceinline__ void cp16(uint32_t dst, const void* src) {
    asm volatile("cp.async.cg.shared.global [%0], [%1], 16;" :: "r"(dst), "l"(src));
}
#define CP_COMMIT() asm volatile("cp.async.commit_group;")
#define CP_WAIT1()  asm volatile("cp.async.wait_group 1;")
#define CP_WAIT0()  asm volatile("cp.async.wait_group 0;")

// ---------------------------------------------------------------------------
// fused split: fp32 -> hi fp16 (+ optional lo); blockIdx.y selects tensor
// ---------------------------------------------------------------------------
__global__ __launch_bounds__(256)
void split4_kernel(const float* __restrict__ i0, const float* __restrict__ i1,
                   const float* __restrict__ i2, const float* __restrict__ i3,
                   __half* __restrict__ hi, __half* __restrict__ lo, int n)
{
    const float* in = (blockIdx.y == 0) ? i0 : (blockIdx.y == 1) ? i1
                    : (blockIdx.y == 2) ? i2 : i3;
    const size_t off = (size_t)blockIdx.y * n;
    int i = (blockIdx.x * 256 + threadIdx.x) * 4;
    if (i >= n) return;
    float4 v = *(const float4*)(in + i);
    __half h[4];
    h[0] = __float2half_rn(v.x);
    h[1] = __float2half_rn(v.y);
    h[2] = __float2half_rn(v.z);
    h[3] = __float2half_rn(v.w);
    *(uint2*)(hi + off + i) = *(uint2*)h;
    if (lo) {
        __half l[4];
        l[0] = __float2half_rn(v.x - __half2float(h[0]));
        l[1] = __float2half_rn(v.y - __half2float(h[1]));
        l[2] = __float2half_rn(v.z - __half2float(h[2]));
        l[3] = __float2half_rn(v.w - __half2float(h[3]));
        *(uint2*)(lo + off + i) = *(uint2*)l;
    }
}

// ---------------------------------------------------------------------------
// 2-term split-fp16 GEMM, K-step 64: out = Ah @ (Wh+Wl)^T + b.
// 256 thr / 8 warps; M=128 x N=64; double-buffered 73.7 KB -> 3 CTAs/SM.
// 128 mma between barriers (vs 48 at K-32) to amortize sync stalls.
// ---------------------------------------------------------------------------
#define G2_AH 0                       // offsets in halves within a stage
#define G2_WH (128 * 72)
#define G2_WL (128 * 72 + 64 * 72)
#define G2_ST (128 * 72 + 2 * 64 * 72)   // 18432 halves per stage

__device__ __forceinline__
void gemm2_body(const __half* Ah, const __half* Wh, const __half* Wl,
                const float* bias, void* outp, int head_layout)
{
    extern __shared__ __half dsm[];

    const int tid  = threadIdx.x;
    const int warp = tid >> 5, lane = tid & 31;
    const int g = lane >> 2, q = lane & 3;
    const int m0 = blockIdx.y * 128;
    const int n0 = blockIdx.x * 64;

    // loaders: A 128x64 halves (2 thr/row, 4 cp16), W 64x64 per split
    // (4 thr/row, 2 cp16 each split)
    const int arow = tid >> 1, acb = (tid & 1) * 32;
    const int wrow = tid >> 2, wcb = (tid & 3) * 16;

    const __half* Agh = Ah + (size_t)(m0 + arow) * ND + acb;
    const __half* Wgh = Wh + (size_t)(n0 + wrow) * ND + wcb;
    const __half* Wgl = Wl + (size_t)(n0 + wrow) * ND + wcb;

    float D[8][4];
#pragma unroll
    for (int nb = 0; nb < 8; nb++)
#pragma unroll
        for (int i = 0; i < 4; i++) D[nb][i] = 0.f;

    auto load_stage = [&](int stage, int k0) {
        __half* base = dsm + (stage & 1) * G2_ST;
        uint32_t ah = cvta_s(base + G2_AH + arow * 72 + acb);
        uint32_t wh = cvta_s(base + G2_WH + wrow * 72 + wcb);
        uint32_t wl = cvta_s(base + G2_WL + wrow * 72 + wcb);
#pragma unroll
        for (int j = 0; j < 4; j++)
            cp16(ah + j * 16, Agh + k0 + j * 8);
#pragma unroll
        for (int j = 0; j < 2; j++) {
            cp16(wh + j * 16, Wgh + k0 + j * 8);
            cp16(wl + j * 16, Wgl + k0 + j * 8);
        }
        CP_COMMIT();
    };

    load_stage(0, 0);
    load_stage(1, 64);

#pragma unroll 1
    for (int it = 0; it < ND / 64; it++) {
        const __half* base = dsm + (it & 1) * G2_ST;

        if (it < ND / 64 - 1) { CP_WAIT1(); } else { CP_WAIT0(); }
        __syncthreads();

#pragma unroll
        for (int kc = 0; kc < 4; kc++) {
            int arw = warp * 16 + (lane & 15);
            int acl = kc * 16 + (lane >> 4) * 8;
            uint32_t ahf[4];
            ldsm4(ahf, cvta_s(base + G2_AH + arw * 72 + acl));
#pragma unroll
            for (int nbp = 0; nbp < 4; nbp++) {
                int row = nbp * 16 + ((lane >> 4) & 1) * 8 + (lane & 7);
                int col = kc * 16 + ((lane >> 3) & 1) * 8;
                uint32_t bh[4], bl[4];
                ldsm4(bh, cvta_s(base + G2_WH + row * 72 + col));
                ldsm4(bl, cvta_s(base + G2_WL + row * 72 + col));
                mma_f16(D[2 * nbp],     ahf, bh[0], bh[1]);
                mma_f16(D[2 * nbp + 1], ahf, bh[2], bh[3]);
                mma_f16(D[2 * nbp],     ahf, bl[0], bl[1]);
                mma_f16(D[2 * nbp + 1], ahf, bl[2], bl[3]);
            }
        }
        __syncthreads();
        if (it + 2 < ND / 64) load_stage(it + 2, (it + 2) * 64);
    }

    // ---- epilogue ----
    const float* bp = bias + n0;
    const int mg = m0 + warp * 16 + g;
#pragma unroll
    for (int nb = 0; nb < 8; nb++) {
        int c = nb * 8 + 2 * q;
        float2 bb = *(const float2*)(bp + c);
        float o00 = D[nb][0] + bb.x, o01 = D[nb][1] + bb.y;   // row mg
        float o10 = D[nb][2] + bb.x, o11 = D[nb][3] + bb.y;   // row mg+8
        if (head_layout) {
            int h = n0 >> 6;
            int bbi = mg >> 12, t = mg & 4095;
            __half* oh = (__half*)outp;
            size_t bse = ((size_t)(bbi * NH + h) * NT + t) * NHD + c;
            *(__half2*)&oh[bse]           = __floats2half2_rn(o00, o01);
            *(__half2*)&oh[bse + 8 * NHD] = __floats2half2_rn(o10, o11);
        } else {
            float* of = (float*)outp;
            size_t bse = (size_t)mg * ND + n0 + c;
            *(float2*)&of[bse]          = make_float2(o00, o01);
            *(float2*)&of[bse + 8 * ND] = make_float2(o10, o11);
        }
    }
}

// fused QKV projections: blockIdx.z selects (activation, weight, bias, out)
__global__ __launch_bounds__(256, 3)
void gemmqkv_kernel(const __half* __restrict__ ah,
                    const __half* __restrict__ wh, const __half* __restrict__ wl,
                    const float* __restrict__ bq, const float* __restrict__ bk,
                    const float* __restrict__ bv,
                    __half* __restrict__ qb, __half* __restrict__ kb,
                    __half* __restrict__ vb)
{
    const int z = blockIdx.z;
    const size_t NAo = (size_t)NB * NT * ND;
    const size_t NWo = (size_t)ND * ND;
    const float* bias = (z == 0) ? bq : (z == 1) ? bk : bv;
    __half* outp = (z == 0) ? qb : (z == 1) ? kb : vb;
    gemm2_body(ah + z * NAo, wh + z * NWo, wl + z * NWo, bias, outp, 1);
}

// Wo projection: A is plain fp16 (attention output), fp32 out
__global__ __launch_bounds__(256, 3)
void gemmwo_kernel(const __half* __restrict__ Ah,
                   const __half* __restrict__ Wh, const __half* __restrict__ Wl,
                   const float* __restrict__ bias, float* __restrict__ outp)
{
    gemm2_body(Ah, Wh, Wl, bias, outp, 0);
}

// ---------------------------------------------------------------------------
// fp16 flash attention v10b: T-tile 128 (256 thr / 8 warps, 16 rows/warp),
// 3-stage ring of 128-deep K/V tiles (110.6 KB dynamic smem, 2 CTAs/SM).
// One barrier per 128 s-cols; two 64-col sub-blocks per barrier.
// FIX vs v10: load_tile covers the FULL 32-half span per thread (4 cp16).
// ---------------------------------------------------------------------------
#define AT_TILE (128 * 72)                // halves per K or V ring slot
#define AT_SMEM (6 * AT_TILE * 2)         // bytes: 110592

__global__ __launch_bounds__(256)
void attn_kernel(const __half* __restrict__ Qh, const __half* __restrict__ Kh,
                 const __half* __restrict__ Vh,
                 const unsigned char* __restrict__ mask,
                 __half* __restrict__ outh)
{
    extern __shared__ __half asmem[];
    __half* Ksm = asmem;                 // [3][128][72]
    __half* Vsm = asmem + 3 * AT_TILE;   // [3][128][72]

    const int b  = blockIdx.z;
    const int h  = blockIdx.y;
    const int t0 = blockIdx.x * 128;
    const int tid  = threadIdx.x;
    const int warp = tid >> 5;
    const int lane = tid & 31;
    const int g = lane >> 2;
    const int q = lane & 3;
    const int w16 = warp * 16;
    const uint32_t ONES = 0x3C003C00u;   // half2(1,1)

    const __half* Kp = Kh + (size_t)(b * NH + h) * NS * NHD;
    const __half* Vp = Vh + (size_t)(b * NH + h) * NS * NHD;
    const unsigned char* mp = mask + (size_t)b * NS;

    const int lrow = tid >> 1;           // 0..127 (2 threads per s-row)
    const int lcol = (tid & 1) * 32;     // halves; each thread owns 32 halves

    auto load_tile = [&](int t) {        // t = 128-deep tile index
        int buf = t % 3;
        const __half* kg = Kp + (size_t)(t * 128 + lrow) * NHD + lcol;
        const __half* vg = Vp + (size_t)(t * 128 + lrow) * NHD + lcol;
        uint32_t kd = cvta_s(Ksm + buf * AT_TILE + lrow * 72 + lcol);
        uint32_t vd = cvta_s(Vsm + buf * AT_TILE + lrow * 72 + lcol);
#pragma unroll
        for (int j = 0; j < 4; j++) {    // 4 x 16B = 32 halves (full span)
            cp16(kd + j * 16, kg + j * 8);
            cp16(vd + j * 16, vg + j * 8);
        }
        CP_COMMIT();
    };

    // ---- per-CTA 64-bit "64-col block has masked column" bitmask ----
    uint64_t mbits;
    {
        const uint4* mq = (const uint4*)mp;          // 4096 B = 256 uint4
        uint4 a = mq[tid];                           // 16 B per thread
        uint32_t o = a.x | a.y | a.z | a.w;
        uint32_t bal = __ballot_sync(0xffffffffu, o != 0u);
        uint32_t t8 = 0;
#pragma unroll
        for (int j = 0; j < 8; j++)
            t8 |= (((bal >> (4 * j)) & 0xFu) ? 1u : 0u) << j;
        __shared__ uint32_t wbits[8];
        if (lane == 0) wbits[warp] = t8;
        __syncthreads();
        mbits = 0;
#pragma unroll
        for (int w = 0; w < 8; w++)
            mbits |= (uint64_t)wbits[w] << (8 * w);
    }

    // ---- Q fragments (fp16 regs, once), scale 0.125*log2(e) ----
    uint32_t Qf[4][4];
    {
        const __half2 qs2 = __float2half2_rn(0.125f * 1.4426950408889634f);
        const __half* Q0 = Qh + ((size_t)(b * NH + h) * NT + t0 + w16 + g) * NHD;
        const __half* Q1 = Q0 + 8 * NHD;
#pragma unroll
        for (int kc = 0; kc < 4; kc++) {
            __half2 x0 = __hmul2(*(const __half2*)(Q0 + kc * 16 + 2 * q),     qs2);
            __half2 x1 = __hmul2(*(const __half2*)(Q1 + kc * 16 + 2 * q),     qs2);
            __half2 x2 = __hmul2(*(const __half2*)(Q0 + kc * 16 + 2 * q + 8), qs2);
            __half2 x3 = __hmul2(*(const __half2*)(Q1 + kc * 16 + 2 * q + 8), qs2);
            Qf[kc][0] = *(uint32_t*)&x0;
            Qf[kc][1] = *(uint32_t*)&x1;
            Qf[kc][2] = *(uint32_t*)&x2;
            Qf[kc][3] = *(uint32_t*)&x3;
        }
    }

    float O[8][4];
#pragma unroll
    for (int nb = 0; nb < 8; nb++)
#pragma unroll
        for (int i = 0; i < 4; i++) O[nb][i] = 0.f;
    float m0 = -INFINITY, m1 = -INFINITY, l0 = 0.f, l1 = 0.f;

    // ---- prologue: async-load 128-deep tiles 0 and 1 ----
    load_tile(0);
    load_tile(1);

#pragma unroll 1
    for (int it = 0; it < NS / 128; it++) {
        const int cur = it % 3;
        if (it < NS / 128 - 1) { CP_WAIT1(); } else { CP_WAIT0(); }
        __syncthreads();   // tile `it` visible; readers of buf (it-1)%3 done
        if (it + 2 < NS / 128) load_tile(it + 2);

#pragma unroll 1
        for (int sub = 0; sub < 2; sub++) {
            const __half* Kcur = Ksm + cur * AT_TILE + sub * 64 * 72;
            const __half* Vcur = Vsm + cur * AT_TILE + sub * 64 * 72;
            const int any = (int)((mbits >> (2 * it + sub)) & 1u);

            // ---- QK^T via ldmatrix(non-trans) B-frags ----
            float D[8][4];
#pragma unroll
            for (int nb = 0; nb < 8; nb++) {
                D[nb][0] = 0.f; D[nb][1] = 0.f; D[nb][2] = 0.f; D[nb][3] = 0.f;
            }
#pragma unroll
            for (int kc = 0; kc < 4; kc++) {
#pragma unroll
                for (int nbp = 0; nbp < 4; nbp++) {
                    int row = nbp * 16 + ((lane >> 4) & 1) * 8 + (lane & 7);
                    int col = kc * 16 + ((lane >> 3) & 1) * 8;
                    uint32_t bf[4];
                    ldsm4(bf, cvta_s(Kcur + row * 72 + col));
                    mma_f16(D[2 * nbp],     Qf[kc], bf[0], bf[1]);
                    mma_f16(D[2 * nbp + 1], Qf[kc], bf[2], bf[3]);
                }
            }

            // ---- mask (rare path: read mask bytes from gmem) ----
            if (any) {
                const unsigned char* Msk = mp + it * 128 + sub * 64;
#pragma unroll
                for (int nb = 0; nb < 8; nb++) {
                    int c0 = nb * 8 + 2 * q;
                    if (Msk[c0])     { D[nb][0] = -INFINITY; D[nb][2] = -INFINITY; }
                    if (Msk[c0 + 1]) { D[nb][1] = -INFINITY; D[nb][3] = -INFINITY; }
                }
            }

            // ---- online softmax (log2 domain); rows g, g+8 ----
            float ml0 = -INFINITY, ml1 = -INFINITY;
#pragma unroll
            for (int nb = 0; nb < 8; nb++) {
                ml0 = fmaxf(ml0, fmaxf(D[nb][0], D[nb][1]));
                ml1 = fmaxf(ml1, fmaxf(D[nb][2], D[nb][3]));
            }
            ml0 = fmaxf(ml0, __shfl_xor_sync(0xffffffffu, ml0, 1));
            ml0 = fmaxf(ml0, __shfl_xor_sync(0xffffffffu, ml0, 2));
            ml1 = fmaxf(ml1, __shfl_xor_sync(0xffffffffu, ml1, 1));
            ml1 = fmaxf(ml1, __shfl_xor_sync(0xffffffffu, ml1, 2));

            float mn0 = fmaxf(m0, ml0), mn1 = fmaxf(m1, ml1);
            float ms0 = (mn0 == -INFINITY) ? 0.f : mn0;
            float ms1 = (mn1 == -INFINITY) ? 0.f : mn1;
#pragma unroll
            for (int nb = 0; nb < 8; nb++) {
                D[nb][0] = ex2f(D[nb][0] - ms0);
                D[nb][1] = ex2f(D[nb][1] - ms0);
                D[nb][2] = ex2f(D[nb][2] - ms1);
                D[nb][3] = ex2f(D[nb][3] - ms1);
            }

            float f0 = ex2f(m0 - ms0);   // exact 1.0 when max unchanged
            float f1 = ex2f(m1 - ms1);
            if (ml0 > m0 || ml1 > m1) {  // rescale only when a max moved
#pragma unroll
                for (int nb = 0; nb < 8; nb++) {
                    O[nb][0] *= f0; O[nb][1] *= f0;
                    O[nb][2] *= f1; O[nb][3] *= f1;
                }
            }
            m0 = mn0; m1 = mn1;

            // ---- O += P @ V ; row sums via P @ ones ----
            float Ssum[4] = {0.f, 0.f, 0.f, 0.f};
#pragma unroll
            for (int kk = 0; kk < 4; kk++) {
                uint32_t a[4];
                a[0] = packh2(D[2 * kk][0],     D[2 * kk][1]);
                a[1] = packh2(D[2 * kk][2],     D[2 * kk][3]);
                a[2] = packh2(D[2 * kk + 1][0], D[2 * kk + 1][1]);
                a[3] = packh2(D[2 * kk + 1][2], D[2 * kk + 1][3]);
                mma_f16(Ssum, a, ONES, ONES);
#pragma unroll
                for (int nbp = 0; nbp < 4; nbp++) {
                    int row = kk * 16 + ((lane >> 3) & 1) * 8 + (lane & 7);
                    int col = nbp * 16 + ((lane >> 4) & 1) * 8;
                    uint32_t bf[4];
                    ldsm4t(bf, cvta_s(Vcur + row * 72 + col));
                    mma_f16(O[2 * nbp],     a, bf[0], bf[1]);
                    mma_f16(O[2 * nbp + 1], a, bf[2], bf[3]);
                }
            }
            l0 = l0 * f0 + Ssum[0];
            l1 = l1 * f1 + Ssum[2];
        }
        // no trailing barrier: next iteration's __syncthreads covers it
    }

    // ---- epilogue: normalize, write plain fp16 at [B*T, D] ----
    {
        float inv0 = (l0 > 0.f) ? (1.0f / l0) : 0.f;
        float inv1 = (l1 > 0.f) ? (1.0f / l1) : 0.f;
        size_t r0 = ((size_t)(b * NT + t0 + w16 + g))     * ND + h * NHD;
        size_t r1 = ((size_t)(b * NT + t0 + w16 + g + 8)) * ND + h * NHD;
#pragma unroll
        for (int nb = 0; nb < 8; nb++) {
            int c = nb * 8 + 2 * q;
            *(__half2*)&outh[r0 + c] =
                __floats2half2_rn(O[nb][0] * inv0, O[nb][1] * inv0);
            *(__half2*)&outh[r1 + c] =
                __floats2half2_rn(O[nb][2] * inv1, O[nb][3] * inv1);
        }
    }
}

// ---------------------------------------------------------------------------
extern "C" void kernel_launch(void* const* d_in, const int* in_sizes, int n_in,
                              void* d_out, int out_size)
{
    const float* query = (const float*)d_in[0];
    const float* key   = (const float*)d_in[1];
    const float* value = (const float*)d_in[2];
    const unsigned char* mask = (const unsigned char*)d_in[3];
    const float* Wq = (const float*)d_in[4];
    const float* bq = (const float*)d_in[5];
    const float* Wk = (const float*)d_in[6];
    const float* bk = (const float*)d_in[7];
    const float* Wv = (const float*)d_in[8];
    const float* bv = (const float*)d_in[9];
    const float* Wo = (const float*)d_in[10];
    const float* bo = (const float*)d_in[11];
    float* out = (float*)d_out;

    __half *qb, *kb, *vb, *ah, *wh, *wl, *oh;
    cudaGetSymbolAddress((void**)&qb, g_q);
    cudaGetSymbolAddress((void**)&kb, g_k);
    cudaGetSymbolAddress((void**)&vb, g_v);
    cudaGetSymbolAddress((void**)&ah, g_ah);
    cudaGetSymbolAddress((void**)&wh, g_wh);
    cudaGetSymbolAddress((void**)&wl, g_wl);
    cudaGetSymbolAddress((void**)&oh, g_oh);

    const int smem2 = G2_ST * 2 * (int)sizeof(__half);   // 73728 B
    cudaFuncSetAttribute(gemmqkv_kernel,
                         cudaFuncAttributeMaxDynamicSharedMemorySize, smem2);
    cudaFuncSetAttribute(gemmwo_kernel,
                         cudaFuncAttributeMaxDynamicSharedMemorySize, smem2);
    cudaFuncSetAttribute(attn_kernel,
                         cudaFuncAttributeMaxDynamicSharedMemorySize, AT_SMEM);

    const int NW = ND * ND;               // 262144 per weight
    const int NA = NB * NT * ND;          // 8388608 per activation

    // fused splits: weights get hi+lo; activations hi only
    split4_kernel<<<dim3(NW / 1024, 4), 256>>>(Wq, Wk, Wv, Wo, wh, wl, NW);
    split4_kernel<<<dim3(NA / 1024, 3), 256>>>(query, key, value, query,
                                               ah, (__half*)nullptr, NA);

    // fused QKV projections (one launch, grid.z selects projection)
    dim3 gq(ND / 64, (NB * NT) / 128, 3);   // (8, 128, 3)
    gemmqkv_kernel<<<gq, 256, smem2>>>(ah, wh, wl, bq, bk, bv, qb, kb, vb);

    dim3 ga(NT / 128, NH, NB);              // (32, 8, 4)
    attn_kernel<<<ga, 256, AT_SMEM>>>(qb, kb, vb, mask, oh);

    dim3 gg(ND / 64, (NB * NT) / 128);      // (8, 128)
    gemmwo_kernel<<<gg, 256, smem2>>>(oh, wh + 3 * NW, wl + 3 * NW, bo, out);
}

// round 17
// speedup vs baseline: 1.1193x; 1.1193x over previous
#include <cuda_runtime.h>
#include <cuda_fp16.h>
#include <math.h>
#include <stdint.h>

#define NB 4
#define NT 4096
#define NS 4096
#define ND 512
#define NH 8
#define NHD 64

// Scratch (allocation-free rule: __device__ globals)
__device__ __half g_q[NB * NH * NT * NHD];
__device__ __half g_k[NB * NH * NS * NHD];
__device__ __half g_v[NB * NH * NS * NHD];
__device__ __half g_ah[3 * NB * NT * ND];   // fp16 query|key|value
__device__ __half g_wh[4 * ND * ND];        // hi split of Wq|Wk|Wv|Wo
__device__ __half g_wl[4 * ND * ND];
__device__ __half g_oh[NB * NT * ND];       // attention output (fp16)

// ===========================================================================
// helpers
// ===========================================================================
__device__ __forceinline__ float ex2f(float x) {
    float y;
    asm("ex2.approx.ftz.f32 %0, %1;" : "=f"(y) : "f"(x));
    return y;
}
__device__ __forceinline__ uint32_t packh2(float lo, float hi) {
    __half2 h = __floats2half2_rn(lo, hi);
    return *reinterpret_cast<uint32_t*>(&h);
}
__device__ __forceinline__ uint32_t cvta_s(const void* p) {
    return (uint32_t)__cvta_generic_to_shared(p);
}
// D += A * B  (m16n8k16 fp16 in, fp32 accum; A row-major, B col-major)
__device__ __forceinline__ void mma_f16(float* d, const uint32_t* a,
                                        uint32_t b0, uint32_t b1) {
    asm volatile(
        "mma.sync.aligned.m16n8k16.row.col.f32.f16.f16.f32 "
        "{%0,%1,%2,%3}, {%4,%5,%6,%7}, {%8,%9}, {%0,%1,%2,%3};"
        : "+f"(d[0]), "+f"(d[1]), "+f"(d[2]), "+f"(d[3])
        : "r"(a[0]), "r"(a[1]), "r"(a[2]), "r"(a[3]), "r"(b0), "r"(b1));
}
__device__ __forceinline__ void ldsm4(uint32_t* r, uint32_t addr) {
    asm volatile("ldmatrix.sync.aligned.m8n8.x4.shared.b16 {%0,%1,%2,%3}, [%4];"
                 : "=r"(r[0]), "=r"(r[1]), "=r"(r[2]), "=r"(r[3]) : "r"(addr));
}
__device__ __forceinline__ void ldsm4t(uint32_t* r, uint32_t addr) {
    asm volatile("ldmatrix.sync.aligned.m8n8.x4.trans.shared.b16 {%0,%1,%2,%3}, [%4];"
                 : "=r"(r[0]), "=r"(r[1]), "=r"(r[2]), "=r"(r[3]) : "r"(addr));
}
__device__ __forceinline__ void cp16(uint32_t dst, const void* src) {
    asm volatile("cp.async.cg.shared.global [%0], [%1], 16;" :: "r"(dst), "l"(src));
}
#define CP_COMMIT() asm volatile("cp.async.commit_group;")
#define CP_WAIT1()  asm volatile("cp.async.wait_group 1;")
#define CP_WAIT0()  asm volatile("cp.async.wait_group 0;")

// ---------------------------------------------------------------------------
// fused split: fp32 -> hi fp16 (+ optional lo); blockIdx.y selects tensor
// ---------------------------------------------------------------------------
__global__ __launch_bounds__(256)
void split4_kernel(const float* __restrict__ i0, const float* __restrict__ i1,
                   const float* __restrict__ i2, const float* __restrict__ i3,
                   __half* __restrict__ hi, __half* __restrict__ lo, int n)
{
    const float* in = (blockIdx.y == 0) ? i0 : (blockIdx.y == 1) ? i1
                    : (blockIdx.y == 2) ? i2 : i3;
    const size_t off = (size_t)blockIdx.y * n;
    int i = (blockIdx.x * 256 + threadIdx.x) * 4;
    if (i >= n) return;
    float4 v = *(const float4*)(in + i);
    __half h[4];
    h[0] = __float2half_rn(v.x);
    h[1] = __float2half_rn(v.y);
    h[2] = __float2half_rn(v.z);
    h[3] = __float2half_rn(v.w);
    *(uint2*)(hi + off + i) = *(uint2*)h;
    if (lo) {
        __half l[4];
        l[0] = __float2half_rn(v.x - __half2float(h[0]));
        l[1] = __float2half_rn(v.y - __half2float(h[1]));
        l[2] = __float2half_rn(v.z - __half2float(h[2]));
        l[3] = __float2half_rn(v.w - __half2float(h[3]));
        *(uint2*)(lo + off + i) = *(uint2*)l;
    }
}

// ---------------------------------------------------------------------------
// 2-term split-fp16 GEMM, K-step 32 (R14 schedule): out = Ah @ (Wh+Wl)^T + b.
// 256 thr / 8 warps; M=128 x N=64; double-buffered 40 KB; launch_bounds
// (256,4) caps regs at 64 -> 4 CTAs/SM (32 warps) for latency hiding.
// ---------------------------------------------------------------------------
#define G2_AH 0                       // offsets in halves within a stage
#define G2_WH (128 * 40)
#define G2_WL (128 * 40 + 64 * 40)
#define G2_ST (128 * 40 + 2 * 64 * 40)   // 10240 halves per stage

__device__ __forceinline__
void gemm2_body(const __half* Ah, const __half* Wh, const __half* Wl,
                const float* bias, void* outp, int head_layout)
{
    extern __shared__ __half dsm[];

    const int tid  = threadIdx.x;
    const int warp = tid >> 5, lane = tid & 31;
    const int g = lane >> 2, q = lane & 3;
    const int m0 = blockIdx.y * 128;
    const int n0 = blockIdx.x * 64;

    const int arow = tid >> 1, acb = (tid & 1) * 16;
    const int wrow = tid >> 2, wcb = (tid & 3) * 8;

    const __half* Agh = Ah + (size_t)(m0 + arow) * ND + acb;
    const __half* Wgh = Wh + (size_t)(n0 + wrow) * ND + wcb;
    const __half* Wgl = Wl + (size_t)(n0 + wrow) * ND + wcb;

    float D[8][4];
#pragma unroll
    for (int nb = 0; nb < 8; nb++)
#pragma unroll
        for (int i = 0; i < 4; i++) D[nb][i] = 0.f;

    auto load_stage = [&](int stage, int k0) {
        __half* base = dsm + (stage & 1) * G2_ST;
        uint32_t ah = cvta_s(base + G2_AH + arow * 40 + acb);
        uint32_t wh = cvta_s(base + G2_WH + wrow * 40 + wcb);
        uint32_t wl = cvta_s(base + G2_WL + wrow * 40 + wcb);
#pragma unroll
        for (int j = 0; j < 2; j++)
            cp16(ah + j * 16, Agh + k0 + j * 8);
        cp16(wh, Wgh + k0);
        cp16(wl, Wgl + k0);
        CP_COMMIT();
    };

    load_stage(0, 0);
    load_stage(1, 32);

#pragma unroll 1
    for (int it = 0; it < ND / 32; it++) {
        const __half* base = dsm + (it & 1) * G2_ST;

        if (it < ND / 32 - 1) { CP_WAIT1(); } else { CP_WAIT0(); }
        __syncthreads();

#pragma unroll
        for (int kc = 0; kc < 2; kc++) {
            int arw = warp * 16 + (lane & 15);
            int acl = kc * 16 + (lane >> 4) * 8;
            uint32_t ahf[4];
            ldsm4(ahf, cvta_s(base + G2_AH + arw * 40 + acl));
#pragma unroll
            for (int nbp = 0; nbp < 4; nbp++) {
                int row = nbp * 16 + ((lane >> 4) & 1) * 8 + (lane & 7);
                int col = kc * 16 + ((lane >> 3) & 1) * 8;
                uint32_t bh[4], bl[4];
                ldsm4(bh, cvta_s(base + G2_WH + row * 40 + col));
                ldsm4(bl, cvta_s(base + G2_WL + row * 40 + col));
                mma_f16(D[2 * nbp],     ahf, bh[0], bh[1]);
                mma_f16(D[2 * nbp + 1], ahf, bh[2], bh[3]);
                mma_f16(D[2 * nbp],     ahf, bl[0], bl[1]);
                mma_f16(D[2 * nbp + 1], ahf, bl[2], bl[3]);
            }
        }
        __syncthreads();
        if (it + 2 < ND / 32) load_stage(it + 2, (it + 2) * 32);
    }

    // ---- epilogue ----
    const float* bp = bias + n0;
    const int mg = m0 + warp * 16 + g;
#pragma unroll
    for (int nb = 0; nb < 8; nb++) {
        int c = nb * 8 + 2 * q;
        float2 bb = *(const float2*)(bp + c);
        float o00 = D[nb][0] + bb.x, o01 = D[nb][1] + bb.y;   // row mg
        float o10 = D[nb][2] + bb.x, o11 = D[nb][3] + bb.y;   // row mg+8
        if (head_layout) {
            int h = n0 >> 6;
            int bbi = mg >> 12, t = mg & 4095;
            __half* oh = (__half*)outp;
            size_t bse = ((size_t)(bbi * NH + h) * NT + t) * NHD + c;
            *(__half2*)&oh[bse]           = __floats2half2_rn(o00, o01);
            *(__half2*)&oh[bse + 8 * NHD] = __floats2half2_rn(o10, o11);
        } else {
            float* of = (float*)outp;
            size_t bse = (size_t)mg * ND + n0 + c;
            *(float2*)&of[bse]          = make_float2(o00, o01);
            *(float2*)&of[bse + 8 * ND] = make_float2(o10, o11);
        }
    }
}

// fused QKV projections: blockIdx.z selects (activation, weight, bias, out)
__global__ __launch_bounds__(256, 4)
void gemmqkv_kernel(const __half* __restrict__ ah,
                    const __half* __restrict__ wh, const __half* __restrict__ wl,
                    const float* __restrict__ bq, const float* __restrict__ bk,
                    const float* __restrict__ bv,
                    __half* __restrict__ qb, __half* __restrict__ kb,
                    __half* __restrict__ vb)
{
    const int z = blockIdx.z;
    const size_t NAo = (size_t)NB * NT * ND;
    const size_t NWo = (size_t)ND * ND;
    const float* bias = (z == 0) ? bq : (z == 1) ? bk : bv;
    __half* outp = (z == 0) ? qb : (z == 1) ? kb : vb;
    gemm2_body(ah + z * NAo, wh + z * NWo, wl + z * NWo, bias, outp, 1);
}

// Wo projection: A is plain fp16 (attention output), fp32 out
__global__ __launch_bounds__(256, 4)
void gemmwo_kernel(const __half* __restrict__ Ah,
                   const __half* __restrict__ Wh, const __half* __restrict__ Wl,
                   const float* __restrict__ bias, float* __restrict__ outp)
{
    gemm2_body(Ah, Wh, Wl, bias, outp, 0);
}

// ---------------------------------------------------------------------------
// fp16 flash attention v9 (R14, proven 426us): T-tile 128 (256 thr / 8 warps,
// 16 rows/warp), 3-stage ring of 64-deep K/V tiles (55.3 KB), one barrier
// per tile, per-CTA 64-bit mask bitmask, fp32 ex2, fp16 output.
// ---------------------------------------------------------------------------
#define AT_TILE (64 * 72)                 // halves per K or V buffer
#define AT_SMEM (6 * AT_TILE * 2)         // bytes: 55296

__global__ __launch_bounds__(256)
void attn_kernel(const __half* __restrict__ Qh, const __half* __restrict__ Kh,
                 const __half* __restrict__ Vh,
                 const unsigned char* __restrict__ mask,
                 __half* __restrict__ outh)
{
    extern __shared__ __half asmem[];
    __half* Ksm = asmem;                 // [3][64][72]
    __half* Vsm = asmem + 3 * AT_TILE;   // [3][64][72]

    const int b  = blockIdx.z;
    const int h  = blockIdx.y;
    const int t0 = blockIdx.x * 128;
    const int tid  = threadIdx.x;
    const int warp = tid >> 5;
    const int lane = tid & 31;
    const int g = lane >> 2;
    const int q = lane & 3;
    const int w16 = warp * 16;
    const uint32_t ONES = 0x3C003C00u;   // half2(1,1)

    const __half* Kp = Kh + (size_t)(b * NH + h) * NS * NHD;
    const __half* Vp = Vh + (size_t)(b * NH + h) * NS * NHD;
    const unsigned char* mp = mask + (size_t)b * NS;

    const int lrow = tid >> 2;           // 0..63 (4 threads per s-row)
    const int lcol = (tid & 3) * 16;     // 0,16,32,48 (halves)

    auto load_tile = [&](int t) {
        int buf = t % 3;
        const __half* kg = Kp + (size_t)(t * 64 + lrow) * NHD + lcol;
        const __half* vg = Vp + (size_t)(t * 64 + lrow) * NHD + lcol;
        uint32_t kd = cvta_s(Ksm + buf * AT_TILE + lrow * 72 + lcol);
        uint32_t vd = cvta_s(Vsm + buf * AT_TILE + lrow * 72 + lcol);
#pragma unroll
        for (int j = 0; j < 2; j++) {
            cp16(kd + j * 16, kg + j * 8);
            cp16(vd + j * 16, vg + j * 8);
        }
        CP_COMMIT();
    };

    // ---- per-CTA 64-bit "tile has masked column" bitmask (computed once) ---
    uint64_t mbits;
    {
        const uint4* mq = (const uint4*)mp;          // 4096 B = 256 uint4
        uint4 a = mq[tid];                           // 16 B per thread
        uint32_t o = a.x | a.y | a.z | a.w;
        uint32_t bal = __ballot_sync(0xffffffffu, o != 0u);
        uint32_t t8 = 0;
#pragma unroll
        for (int j = 0; j < 8; j++)
            t8 |= (((bal >> (4 * j)) & 0xFu) ? 1u : 0u) << j;
        __shared__ uint32_t wbits[8];
        if (lane == 0) wbits[warp] = t8;
        __syncthreads();
        mbits = 0;
#pragma unroll
        for (int w = 0; w < 8; w++)
            mbits |= (uint64_t)wbits[w] << (8 * w);
    }

    // ---- Q fragments (fp16 regs, once), scale 0.125*log2(e) ----
    uint32_t Qf[4][4];
    {
        const __half2 qs2 = __float2half2_rn(0.125f * 1.4426950408889634f);
        const __half* Q0 = Qh + ((size_t)(b * NH + h) * NT + t0 + w16 + g) * NHD;
        const __half* Q1 = Q0 + 8 * NHD;
#pragma unroll
        for (int kc = 0; kc < 4; kc++) {
            __half2 x0 = __hmul2(*(const __half2*)(Q0 + kc * 16 + 2 * q),     qs2);
            __half2 x1 = __hmul2(*(const __half2*)(Q1 + kc * 16 + 2 * q),     qs2);
            __half2 x2 = __hmul2(*(const __half2*)(Q0 + kc * 16 + 2 * q + 8), qs2);
            __half2 x3 = __hmul2(*(const __half2*)(Q1 + kc * 16 + 2 * q + 8), qs2);
            Qf[kc][0] = *(uint32_t*)&x0;
            Qf[kc][1] = *(uint32_t*)&x1;
            Qf[kc][2] = *(uint32_t*)&x2;
            Qf[kc][3] = *(uint32_t*)&x3;
        }
    }

    float O[8][4];
#pragma unroll
    for (int nb = 0; nb < 8; nb++)
#pragma unroll
        for (int i = 0; i < 4; i++) O[nb][i] = 0.f;
    float m0 = -INFINITY, m1 = -INFINITY, l0 = 0.f, l1 = 0.f;

    // ---- prologue: async-load tiles 0 and 1 ----
    load_tile(0);
    load_tile(1);

#pragma unroll 1
    for (int it = 0; it < NS / 64; it++) {
        const int cur = it % 3;
        if (it < NS / 64 - 1) { CP_WAIT1(); } else { CP_WAIT0(); }
        __syncthreads();   // tile `it` visible; readers of buf (it-1)%3 done
        const int any = (int)((mbits >> it) & 1u);
        if (it + 2 < NS / 64) load_tile(it + 2);

        const __half* Kcur = Ksm + cur * AT_TILE;
        const __half* Vcur = Vsm + cur * AT_TILE;

        // ---- QK^T via ldmatrix(non-trans) B-frags ----
        float D[8][4];
#pragma unroll
        for (int nb = 0; nb < 8; nb++) {
            D[nb][0] = 0.f; D[nb][1] = 0.f; D[nb][2] = 0.f; D[nb][3] = 0.f;
        }
#pragma unroll
        for (int kc = 0; kc < 4; kc++) {
#pragma unroll
            for (int nbp = 0; nbp < 4; nbp++) {
                int row = nbp * 16 + ((lane >> 4) & 1) * 8 + (lane & 7);
                int col = kc * 16 + ((lane >> 3) & 1) * 8;
                uint32_t bf[4];
                ldsm4(bf, cvta_s(Kcur + row * 72 + col));
                mma_f16(D[2 * nbp],     Qf[kc], bf[0], bf[1]);
                mma_f16(D[2 * nbp + 1], Qf[kc], bf[2], bf[3]);
            }
        }

        // ---- mask (rare path: read mask bytes from gmem) ----
        if (any) {
            const unsigned char* Msk = mp + it * 64;
#pragma unroll
            for (int nb = 0; nb < 8; nb++) {
                int c0 = nb * 8 + 2 * q;
                if (Msk[c0])     { D[nb][0] = -INFINITY; D[nb][2] = -INFINITY; }
                if (Msk[c0 + 1]) { D[nb][1] = -INFINITY; D[nb][3] = -INFINITY; }
            }
        }

        // ---- online softmax (log2 domain); rows g, g+8 ----
        float ml0 = -INFINITY, ml1 = -INFINITY;
#pragma unroll
        for (int nb = 0; nb < 8; nb++) {
            ml0 = fmaxf(ml0, fmaxf(D[nb][0], D[nb][1]));
            ml1 = fmaxf(ml1, fmaxf(D[nb][2], D[nb][3]));
        }
        ml0 = fmaxf(ml0, __shfl_xor_sync(0xffffffffu, ml0, 1));
        ml0 = fmaxf(ml0, __shfl_xor_sync(0xffffffffu, ml0, 2));
        ml1 = fmaxf(ml1, __shfl_xor_sync(0xffffffffu, ml1, 1));
        ml1 = fmaxf(ml1, __shfl_xor_sync(0xffffffffu, ml1, 2));

        float mn0 = fmaxf(m0, ml0), mn1 = fmaxf(m1, ml1);
        float ms0 = (mn0 == -INFINITY) ? 0.f : mn0;
        float ms1 = (mn1 == -INFINITY) ? 0.f : mn1;
#pragma unroll
        for (int nb = 0; nb < 8; nb++) {
            D[nb][0] = ex2f(D[nb][0] - ms0);
            D[nb][1] = ex2f(D[nb][1] - ms0);
            D[nb][2] = ex2f(D[nb][2] - ms1);
            D[nb][3] = ex2f(D[nb][3] - ms1);
        }

        float f0 = ex2f(m0 - ms0);   // exact 1.0 when max unchanged
        float f1 = ex2f(m1 - ms1);
        if (ml0 > m0 || ml1 > m1) {  // rescale only when a max moved
#pragma unroll
            for (int nb = 0; nb < 8; nb++) {
                O[nb][0] *= f0; O[nb][1] *= f0;
                O[nb][2] *= f1; O[nb][3] *= f1;
            }
        }
        m0 = mn0; m1 = mn1;

        // ---- O += P @ V ; row sums via P @ ones ----
        float Ssum[4] = {0.f, 0.f, 0.f, 0.f};
#pragma unroll
        for (int kk = 0; kk < 4; kk++) {
            uint32_t a[4];
            a[0] = packh2(D[2 * kk][0],     D[2 * kk][1]);
            a[1] = packh2(D[2 * kk][2],     D[2 * kk][3]);
            a[2] = packh2(D[2 * kk + 1][0], D[2 * kk + 1][1]);
            a[3] = packh2(D[2 * kk + 1][2], D[2 * kk + 1][3]);
            mma_f16(Ssum, a, ONES, ONES);
#pragma unroll
            for (int nbp = 0; nbp < 4; nbp++) {
                int row = kk * 16 + ((lane >> 3) & 1) * 8 + (lane & 7);
                int col = nbp * 16 + ((lane >> 4) & 1) * 8;
                uint32_t bf[4];
                ldsm4t(bf, cvta_s(Vcur + row * 72 + col));
                mma_f16(O[2 * nbp],     a, bf[0], bf[1]);
                mma_f16(O[2 * nbp + 1], a, bf[2], bf[3]);
            }
        }
        l0 = l0 * f0 + Ssum[0];
        l1 = l1 * f1 + Ssum[2];
        // no trailing barrier: next iteration's __syncthreads covers it
    }

    // ---- epilogue: normalize, write plain fp16 at [B*T, D] ----
    {
        float inv0 = (l0 > 0.f) ? (1.0f / l0) : 0.f;
        float inv1 = (l1 > 0.f) ? (1.0f / l1) : 0.f;
        size_t r0 = ((size_t)(b * NT + t0 + w16 + g))     * ND + h * NHD;
        size_t r1 = ((size_t)(b * NT + t0 + w16 + g + 8)) * ND + h * NHD;
#pragma unroll
        for (int nb = 0; nb < 8; nb++) {
            int c = nb * 8 + 2 * q;
            *(__half2*)&outh[r0 + c] =
                __floats2half2_rn(O[nb][0] * inv0, O[nb][1] * inv0);
            *(__half2*)&outh[r1 + c] =
                __floats2half2_rn(O[nb][2] * inv1, O[nb][3] * inv1);
        }
    }
}

// ---------------------------------------------------------------------------
extern "C" void kernel_launch(void* const* d_in, const int* in_sizes, int n_in,
                              void* d_out, int out_size)
{
    const float* query = (const float*)d_in[0];
    const float* key   = (const float*)d_in[1];
    const float* value = (const float*)d_in[2];
    const unsigned char* mask = (const unsigned char*)d_in[3];
    const float* Wq = (const float*)d_in[4];
    const float* bq = (const float*)d_in[5];
    const float* Wk = (const float*)d_in[6];
    const float* bk = (const float*)d_in[7];
    const float* Wv = (const float*)d_in[8];
    const float* bv = (const float*)d_in[9];
    const float* Wo = (const float*)d_in[10];
    const float* bo = (const float*)d_in[11];
    float* out = (float*)d_out;

    __half *qb, *kb, *vb, *ah, *wh, *wl, *oh;
    cudaGetSymbolAddress((void**)&qb, g_q);
    cudaGetSymbolAddress((void**)&kb, g_k);
    cudaGetSymbolAddress((void**)&vb, g_v);
    cudaGetSymbolAddress((void**)&ah, g_ah);
    cudaGetSymbolAddress((void**)&wh, g_wh);
    cudaGetSymbolAddress((void**)&wl, g_wl);
    cudaGetSymbolAddress((void**)&oh, g_oh);

    const int smem2 = G2_ST * 2 * (int)sizeof(__half);   // 40960 B
    cudaFuncSetAttribute(gemmqkv_kernel,
                         cudaFuncAttributeMaxDynamicSharedMemorySize, smem2);
    cudaFuncSetAttribute(gemmwo_kernel,
                         cudaFuncAttributeMaxDynamicSharedMemorySize, smem2);
    cudaFuncSetAttribute(attn_kernel,
                         cudaFuncAttributeMaxDynamicSharedMemorySize, AT_SMEM);

    const int NW = ND * ND;               // 262144 per weight
    const int NA = NB * NT * ND;          // 8388608 per activation

    // fused splits: weights get hi+lo; activations hi only
    split4_kernel<<<dim3(NW / 1024, 4), 256>>>(Wq, Wk, Wv, Wo, wh, wl, NW);
    split4_kernel<<<dim3(NA / 1024, 3), 256>>>(query, key, value, query,
                                               ah, (__half*)nullptr, NA);

    // fused QKV projections (one launch, grid.z selects projection)
    dim3 gq(ND / 64, (NB * NT) / 128, 3);   // (8, 128, 3)
    gemmqkv_kernel<<<gq, 256, smem2>>>(ah, wh, wl, bq, bk, bv, qb, kb, vb);

    dim3 ga(NT / 128, NH, NB);              // (32, 8, 4)
    attn_kernel<<<ga, 256, AT_SMEM>>>(qb, kb, vb, mask, oh);

    dim3 gg(ND / 64, (NB * NT) / 128);      // (8, 128)
    gemmwo_kernel<<<gg, 256, smem2>>>(oh, wh + 3 * NW, wl + 3 * NW, bo, out);
}